// round 14
// baseline (speedup 1.0000x reference)
#include <cuda_runtime.h>
#include <cuda_bf16.h>

#define NN 256
#define CIN 128
#define CATT 32
#define NH 4
#define LN_EPS 1e-5f
#define KSS 40        // Ks bf16 stride (k2)
#define VTS 264       // Vt bf16 stride (k2)
#define OSTR 136      // bf16 smem stride (k1/k3)
#define LOG2E 1.4426950408889634f
#define QSC 0.25502551286804425f   // (1/sqrt(32))*log2e

// ---------------- scratch (device globals; allocation-free rule) ------------
__device__ __nv_bfloat16 g_q   [(size_t)NN*NH*NN*CATT];  // [i][h][j][c]
__device__ __nv_bfloat16 g_k   [(size_t)NN*NH*NN*CATT];
__device__ __nv_bfloat16 g_v   [(size_t)NN*NH*NN*CATT];
__device__ __nv_bfloat16 g_gate[(size_t)NN*NH*NN*CATT];
__device__ __nv_bfloat16 g_ao  [(size_t)NN*NH*NN*CATT];  // [i][h][j][c]
__device__ __nv_bfloat16 g_B2t [(size_t)NH*NN*NN];       // [h][j][k] * log2e, bf16
__device__ __nv_bfloat16 g_Wb  [4*128*128];              // bf16 [t][n][k] (k1)
__device__ __nv_bfloat16 g_Wo  [128*128];                // bf16 [n][k] (k3)

__device__ __forceinline__ float ex2(float x) {
    float y;
    asm("ex2.approx.ftz.f32 %0, %1;" : "=f"(y) : "f"(x));
    return y;
}
__device__ __forceinline__ unsigned pack_bf16(float lo, float hi) {
    unsigned r;
    asm("cvt.rn.bf16x2.f32 %0, %1, %2;" : "=r"(r) : "f"(hi), "f"(lo));
    return r;
}
__device__ __forceinline__ void mma_bf16(float* d, const unsigned* a, const unsigned* b) {
    asm volatile(
        "mma.sync.aligned.m16n8k16.row.col.f32.bf16.bf16.f32 "
        "{%0,%1,%2,%3}, {%4,%5,%6,%7}, {%8,%9}, {%0,%1,%2,%3};"
        : "+f"(d[0]), "+f"(d[1]), "+f"(d[2]), "+f"(d[3])
        : "r"(a[0]), "r"(a[1]), "r"(a[2]), "r"(a[3]), "r"(b[0]), "r"(b[1]));
}

// ---------------------------------------------------------------------------
// Weight prep: bf16 [t][n][k] (qkv/gate) and [n][k] (Wout, rows remapped)
// ---------------------------------------------------------------------------
__global__ void k_prep(const float* __restrict__ Wqkv,
                       const float* __restrict__ Wgate,
                       const float* __restrict__ Wout)
{
    int gid = blockIdx.x * 256 + threadIdx.x;
    if (gid >= 5 * 16384) return;
    int t = gid >> 14, r = gid & 16383, n = r >> 7, k = r & 127;
    if (t < 3) {
        float v = Wqkv[k*384 + (n & 31)*12 + t*4 + (n >> 5)];
        g_Wb[t*16384 + n*128 + k] = __float2bfloat16(v);
    } else if (t == 3) {
        float v = Wgate[k*128 + (n & 31)*4 + (n >> 5)];
        g_Wb[3*16384 + n*128 + k] = __float2bfloat16(v);
    } else {
        float v = Wout[((k & 31)*4 + (k >> 5))*128 + n];
        g_Wo[n*128 + k] = __float2bfloat16(v);
    }
}

// ---------------------------------------------------------------------------
// Kernel 1: LN (fused) + bf16 GEMM m16n8k16, 64 pixels x 4x128 cols, K=128.
// (R8 exact)
// ---------------------------------------------------------------------------
__global__ void __launch_bounds__(256, 3)
k1_mma(const float* __restrict__ x2d, const float* __restrict__ lng,
       const float* __restrict__ lnb, const float* __restrict__ Wbias,
       const float* __restrict__ bgate)
{
    extern __shared__ char smc[];
    __nv_bfloat16* As = reinterpret_cast<__nv_bfloat16*>(smc);             // [64][OSTR]
    __nv_bfloat16* Bs = reinterpret_cast<__nv_bfloat16*>(smc + 64*OSTR*2); // [128][OSTR]

    const int tid = threadIdx.x, lane = tid & 31, warp = tid >> 5;
    const int pixBase = blockIdx.x * 64;
    const int i = pixBase >> 8, j0 = pixBase & 255;

    // ---- LayerNorm warp-per-pixel + bias projection ----
    for (int p = warp; p < 64; p += 8) {
        const int pix = pixBase + p;
        float4 v = reinterpret_cast<const float4*>(x2d + (size_t)pix*CIN)[lane];
        float s  = v.x + v.y + v.z + v.w;
        float ss = v.x*v.x + v.y*v.y + v.z*v.z + v.w*v.w;
        #pragma unroll
        for (int o = 16; o > 0; o >>= 1) {
            s  += __shfl_xor_sync(0xffffffffu, s,  o);
            ss += __shfl_xor_sync(0xffffffffu, ss, o);
        }
        float mu   = s * (1.f/CIN);
        float rstd = rsqrtf(ss * (1.f/CIN) - mu*mu + LN_EPS);
        float4 g4 = reinterpret_cast<const float4*>(lng)[lane];
        float4 b4 = reinterpret_cast<const float4*>(lnb)[lane];
        float xn[4];
        xn[0] = (v.x - mu)*rstd*g4.x + b4.x;
        xn[1] = (v.y - mu)*rstd*g4.y + b4.y;
        xn[2] = (v.z - mu)*rstd*g4.z + b4.z;
        xn[3] = (v.w - mu)*rstd*g4.w + b4.w;

        unsigned* ap = reinterpret_cast<unsigned*>(As + p*OSTR + lane*4);
        ap[0] = pack_bf16(xn[0], xn[1]);
        ap[1] = pack_bf16(xn[2], xn[3]);

        float bs[NH] = {0.f, 0.f, 0.f, 0.f};
        #pragma unroll
        for (int c = 0; c < 4; c++) {
            float4 wb = reinterpret_cast<const float4*>(Wbias)[lane*4 + c];
            bs[0] += xn[c]*wb.x; bs[1] += xn[c]*wb.y;
            bs[2] += xn[c]*wb.z; bs[3] += xn[c]*wb.w;
        }
        #pragma unroll
        for (int o = 16; o > 0; o >>= 1) {
            #pragma unroll
            for (int h = 0; h < NH; h++) bs[h] += __shfl_xor_sync(0xffffffffu, bs[h], o);
        }
        if (lane < 4)
            g_B2t[((size_t)lane*NN + (pix & 255))*NN + (pix >> 8)] =
                __float2bfloat16(bs[lane] * LOG2E);
    }

    const int wm = warp >> 1, wn = warp & 1;
    const int grp = lane >> 2, qd = lane & 3;
    const int rb = wm*16;
    const int row0 = rb + grp;

    for (int tile = 0; tile < 4; tile++) {
        const __nv_bfloat16* Wt = g_Wb + tile*16384;
        for (int e = tid; e < 2048; e += 256) {
            int n = e >> 4, ch = e & 15;
            uint4 v = *reinterpret_cast<const uint4*>(Wt + n*128 + ch*8);
            *reinterpret_cast<uint4*>(Bs + n*OSTR + ch*8) = v;
        }
        __syncthreads();

        float d[8][4];
        #pragma unroll
        for (int ni = 0; ni < 8; ni++)
            #pragma unroll
            for (int r = 0; r < 4; r++) d[ni][r] = 0.f;

        #pragma unroll 2
        for (int kc = 0; kc < 8; kc++) {
            const int k0 = kc*16;
            unsigned a[4];
            a[0] = *reinterpret_cast<const unsigned*>(As + (rb + grp    )*OSTR + k0 + 2*qd);
            a[1] = *reinterpret_cast<const unsigned*>(As + (rb + 8 + grp)*OSTR + k0 + 2*qd);
            a[2] = *reinterpret_cast<const unsigned*>(As + (rb + grp    )*OSTR + k0 + 2*qd + 8);
            a[3] = *reinterpret_cast<const unsigned*>(As + (rb + 8 + grp)*OSTR + k0 + 2*qd + 8);
            unsigned b[8][2];
            #pragma unroll
            for (int ni = 0; ni < 8; ni++) {
                int nb = wn*64 + ni*8 + grp;
                b[ni][0] = *reinterpret_cast<const unsigned*>(Bs + nb*OSTR + k0 + 2*qd);
                b[ni][1] = *reinterpret_cast<const unsigned*>(Bs + nb*OSTR + k0 + 2*qd + 8);
            }
            #pragma unroll
            for (int ni = 0; ni < 8; ni++)
                mma_bf16(d[ni], a, b[ni]);
        }

        if (tile < 3) {
            __nv_bfloat16* dst = (tile == 0) ? g_q : (tile == 1) ? g_k : g_v;
            #pragma unroll
            for (int ni = 0; ni < 8; ni++) {
                int n0 = wn*64 + ni*8 + qd*2;
                int h = n0 >> 5, c = n0 & 31;
                __nv_bfloat16* p0 = dst + ((size_t)(i*NH + h)*NN + j0 + row0)*CATT + c;
                *reinterpret_cast<unsigned*>(p0)          = pack_bf16(d[ni][0], d[ni][1]);
                *reinterpret_cast<unsigned*>(p0 + 8*CATT) = pack_bf16(d[ni][2], d[ni][3]);
            }
        } else {
            #pragma unroll
            for (int ni = 0; ni < 8; ni++) {
                int n0 = wn*64 + ni*8 + qd*2;
                int h = n0 >> 5, c = n0 & 31;
                float bg0 = bgate[c*NH + h], bg1 = bgate[(c+1)*NH + h];
                __nv_bfloat16* p0 = g_gate + ((size_t)(i*NH + h)*NN + j0 + row0)*CATT + c;
                *reinterpret_cast<unsigned*>(p0) = pack_bf16(
                    1.f / (1.f + __expf(-(d[ni][0] + bg0))),
                    1.f / (1.f + __expf(-(d[ni][1] + bg1))));
                *reinterpret_cast<unsigned*>(p0 + 8*CATT) = pack_bf16(
                    1.f / (1.f + __expf(-(d[ni][2] + bg0))),
                    1.f / (1.f + __expf(-(d[ni][3] + bg1))));
            }
        }
        __syncthreads();
    }
}

// ---------------------------------------------------------------------------
// Kernel 2: bf16 flash attention, software-pipelined chunk loop.
// Per body: bias LDGs issued first, QK MMAs for NEXT chunk overlap the
// softmax+PV of the CURRENT chunk (S fragments double-buffered sA/sB).
// ---------------------------------------------------------------------------
#define K2_BODY(KB, SC, SN)                                                        \
    do {                                                                           \
        unsigned bv[8];                                                            \
        _Pragma("unroll")                                                          \
        for (int mi = 0; mi < 2; mi++) {                                           \
            int r0 = qb + mi*16 + grp;                                             \
            _Pragma("unroll")                                                      \
            for (int ni = 0; ni < 2; ni++) {                                       \
                bv[mi*4+ni*2+0] = *reinterpret_cast<const unsigned*>(              \
                    Bt + (size_t)r0*NN + (KB) + ni*8 + 2*qd);                      \
                bv[mi*4+ni*2+1] = *reinterpret_cast<const unsigned*>(              \
                    Bt + (size_t)(r0+8)*NN + (KB) + ni*8 + 2*qd);                  \
            }                                                                      \
        }                                                                          \
        if ((KB) + 16 < NN) {                                                      \
            _Pragma("unroll")                                                      \
            for (int mi = 0; mi < 2; mi++)                                         \
                _Pragma("unroll")                                                  \
                for (int ni = 0; ni < 2; ni++)                                     \
                    _Pragma("unroll")                                              \
                    for (int r = 0; r < 4; r++) SN[mi][ni][r] = 0.f;               \
            _Pragma("unroll")                                                      \
            for (int kc = 0; kc < 2; kc++)                                         \
                _Pragma("unroll")                                                  \
                for (int ni = 0; ni < 2; ni++) {                                   \
                    const __nv_bfloat16* kp =                                      \
                        Ks + ((KB) + 16 + ni*8 + grp)*KSS + kc*16 + 2*qd;          \
                    unsigned b[2];                                                 \
                    b[0] = *reinterpret_cast<const unsigned*>(kp);                 \
                    b[1] = *reinterpret_cast<const unsigned*>(kp + 8);             \
                    mma_bf16(SN[0][ni], aq[kc][0], b);                             \
                    mma_bf16(SN[1][ni], aq[kc][1], b);                             \
                }                                                                  \
        }                                                                          \
        unsigned aP[2][4];                                                         \
        _Pragma("unroll")                                                          \
        for (int mi = 0; mi < 2; mi++) {                                           \
            float pv[2][4];                                                        \
            _Pragma("unroll")                                                      \
            for (int ni = 0; ni < 2; ni++) {                                       \
                __nv_bfloat162 bA =                                                \
                    *reinterpret_cast<__nv_bfloat162*>(&bv[mi*4+ni*2+0]);          \
                __nv_bfloat162 bB =                                                \
                    *reinterpret_cast<__nv_bfloat162*>(&bv[mi*4+ni*2+1]);          \
                pv[ni][0] = ex2(fmaf(SC[mi][ni][0], QSC, __bfloat162float(bA.x))); \
                pv[ni][1] = ex2(fmaf(SC[mi][ni][1], QSC, __bfloat162float(bA.y))); \
                pv[ni][2] = ex2(fmaf(SC[mi][ni][2], QSC, __bfloat162float(bB.x))); \
                pv[ni][3] = ex2(fmaf(SC[mi][ni][3], QSC, __bfloat162float(bB.y))); \
                l[2*mi]   += pv[ni][0] + pv[ni][1];                                \
                l[2*mi+1] += pv[ni][2] + pv[ni][3];                                \
            }                                                                      \
            aP[mi][0] = pack_bf16(pv[0][0], pv[0][1]);                             \
            aP[mi][1] = pack_bf16(pv[0][2], pv[0][3]);                             \
            aP[mi][2] = pack_bf16(pv[1][0], pv[1][1]);                             \
            aP[mi][3] = pack_bf16(pv[1][2], pv[1][3]);                             \
        }                                                                          \
        _Pragma("unroll")                                                          \
        for (int nj = 0; nj < 4; nj++) {                                           \
            const __nv_bfloat16* vp = Vt + (nj*8 + grp)*VTS + (KB) + 2*qd;         \
            unsigned b[2];                                                         \
            b[0] = *reinterpret_cast<const unsigned*>(vp);                         \
            b[1] = *reinterpret_cast<const unsigned*>(vp + 8);                     \
            mma_bf16(o[0][nj], aP[0], b);                                          \
            mma_bf16(o[1][nj], aP[1], b);                                          \
        }                                                                          \
    } while (0)

__global__ void __launch_bounds__(256, 2)
k2_mma()
{
    extern __shared__ char smc[];
    __nv_bfloat16* Ks = reinterpret_cast<__nv_bfloat16*>(smc);            // [256][KSS]
    __nv_bfloat16* Vt = reinterpret_cast<__nv_bfloat16*>(smc + 256*KSS*2);// [32][VTS]

    const int i = blockIdx.x, h = blockIdx.y;
    const int tid = threadIdx.x;
    const size_t base = ((size_t)(i*NH + h))*NN*CATT;

    for (int e = tid; e < 1024; e += 256) {
        int row = e >> 2, c0 = (e & 3) * 8;
        uint4 v = *reinterpret_cast<const uint4*>(g_k + base + row*CATT + c0);
        *reinterpret_cast<uint4*>(Ks + row*KSS + c0) = v;
    }
    for (int e = tid; e < 1024; e += 256) {
        int lane32 = e & 31, grp32 = e >> 5;
        int c0 = (grp32 & 3) * 8, row = (grp32 >> 2) * 32 + lane32;
        uint4 v = *reinterpret_cast<const uint4*>(g_v + base + row*CATT + c0);
        __nv_bfloat16 tmp[8];
        *reinterpret_cast<uint4*>(tmp) = v;
        #pragma unroll
        for (int u = 0; u < 8; u++) Vt[(c0+u)*VTS + row] = tmp[u];
    }

    const int lane = tid & 31, warp = tid >> 5, grp = lane >> 2, qd = lane & 3;
    const int qb = warp*32;

    unsigned aq[2][2][4];
    {
        const __nv_bfloat16* qg = g_q + base;
        #pragma unroll
        for (int kc = 0; kc < 2; kc++)
            #pragma unroll
            for (int mi = 0; mi < 2; mi++) {
                int r0 = qb + mi*16 + grp;
                aq[kc][mi][0] = *reinterpret_cast<const unsigned*>(qg + r0*CATT     + kc*16 + 2*qd);
                aq[kc][mi][1] = *reinterpret_cast<const unsigned*>(qg + (r0+8)*CATT + kc*16 + 2*qd);
                aq[kc][mi][2] = *reinterpret_cast<const unsigned*>(qg + r0*CATT     + kc*16 + 2*qd + 8);
                aq[kc][mi][3] = *reinterpret_cast<const unsigned*>(qg + (r0+8)*CATT + kc*16 + 2*qd + 8);
            }
    }
    __syncthreads();

    float l[4] = {0.f, 0.f, 0.f, 0.f};
    float o[2][4][4];
    #pragma unroll
    for (int mi = 0; mi < 2; mi++)
        #pragma unroll
        for (int nj = 0; nj < 4; nj++)
            #pragma unroll
            for (int r = 0; r < 4; r++) o[mi][nj][r] = 0.f;

    const __nv_bfloat16* Bt = g_B2t + (size_t)h*NN*NN;

    // ---- prologue: QK for chunk 0 into sA ----
    float sA[2][2][4], sB[2][2][4];
    #pragma unroll
    for (int mi = 0; mi < 2; mi++)
        #pragma unroll
        for (int ni = 0; ni < 2; ni++)
            #pragma unroll
            for (int r = 0; r < 4; r++) sA[mi][ni][r] = 0.f;
    #pragma unroll
    for (int kc = 0; kc < 2; kc++)
        #pragma unroll
        for (int ni = 0; ni < 2; ni++) {
            const __nv_bfloat16* kp = Ks + (ni*8 + grp)*KSS + kc*16 + 2*qd;
            unsigned b[2];
            b[0] = *reinterpret_cast<const unsigned*>(kp);
            b[1] = *reinterpret_cast<const unsigned*>(kp + 8);
            mma_bf16(sA[0][ni], aq[kc][0], b);
            mma_bf16(sA[1][ni], aq[kc][1], b);
        }

    // ---- pipelined mainloop (2 bodies per iteration, ping-pong buffers) ----
    for (int kb = 0; kb < NN; kb += 32) {
        K2_BODY(kb,      sA, sB);
        K2_BODY(kb + 16, sB, sA);
    }

    float rl[4];
    #pragma unroll
    for (int r = 0; r < 4; r++) {
        l[r] += __shfl_xor_sync(0xffffffffu, l[r], 1);
        l[r] += __shfl_xor_sync(0xffffffffu, l[r], 2);
        rl[r] = 1.f / l[r];
    }
    #pragma unroll
    for (int mi = 0; mi < 2; mi++) {
        int r0 = qb + mi*16 + grp;
        #pragma unroll
        for (int nj = 0; nj < 4; nj++) {
            int c0 = nj*8 + 2*qd;
            __nv_bfloat162 g0 = *reinterpret_cast<const __nv_bfloat162*>(g_gate + base + (size_t)r0*CATT + c0);
            __nv_bfloat162 g1 = *reinterpret_cast<const __nv_bfloat162*>(g_gate + base + (size_t)(r0+8)*CATT + c0);
            *reinterpret_cast<unsigned*>(g_ao + base + (size_t)r0*CATT + c0) =
                pack_bf16(o[mi][nj][0]*rl[2*mi]  *__bfloat162float(g0.x),
                          o[mi][nj][1]*rl[2*mi]  *__bfloat162float(g0.y));
            *reinterpret_cast<unsigned*>(g_ao + base + (size_t)(r0+8)*CATT + c0) =
                pack_bf16(o[mi][nj][2]*rl[2*mi+1]*__bfloat162float(g1.x),
                          o[mi][nj][3]*rl[2*mi+1]*__bfloat162float(g1.y));
        }
    }
}

// ---------------------------------------------------------------------------
// Kernel 3: out = ao @ Wo + b_out (bf16 mma, R8 exact). 2 M-tiles per CTA.
// ---------------------------------------------------------------------------
__global__ void __launch_bounds__(256, 2)
k3_mma(const float* __restrict__ bout, float* __restrict__ out)
{
    extern __shared__ char smc[];
    __nv_bfloat16* As = reinterpret_cast<__nv_bfloat16*>(smc);            // [64][OSTR]
    __nv_bfloat16* Bs = reinterpret_cast<__nv_bfloat16*>(smc + 64*OSTR*2);// [128][OSTR] ([n][k])

    const int tid = threadIdx.x;
    const int warp = tid >> 5, lane = tid & 31;
    const int wm = warp >> 1, wn = warp & 1;
    const int grp = lane >> 2, qd = lane & 3;
    const int row0 = wm*16 + grp;
    const int rb = wm*16;

    for (int e = tid; e < 2048; e += 256) {
        int n = e >> 4, ch = e & 15;
        uint4 v = *reinterpret_cast<const uint4*>(g_Wo + n*128 + ch*8);
        *reinterpret_cast<uint4*>(Bs + n*OSTR + ch*8) = v;
    }

    float bo[8][2];
    #pragma unroll
    for (int ni = 0; ni < 8; ni++) {
        int n0 = wn*64 + ni*8 + qd*2;
        bo[ni][0] = bout[n0]; bo[ni][1] = bout[n0+1];
    }

    for (int mt = 0; mt < 2; mt++) {
        const int pixBase = blockIdx.x * 128 + mt * 64;
        const int i = pixBase >> 8, j0 = pixBase & 255;

        for (int e = tid; e < 1024; e += 256) {
            int m = e >> 4, u = e & 15, h = u >> 2, c8 = (u & 3) * 8;
            uint4 v = *reinterpret_cast<const uint4*>(
                g_ao + ((size_t)(i*NH + h)*NN + j0 + m)*CATT + c8);
            *reinterpret_cast<uint4*>(As + m*OSTR + h*32 + c8) = v;
        }
        __syncthreads();

        float d[8][4];
        #pragma unroll
        for (int ni = 0; ni < 8; ni++)
            #pragma unroll
            for (int r = 0; r < 4; r++) d[ni][r] = 0.f;

        #pragma unroll 2
        for (int kc = 0; kc < 8; kc++) {
            const int k0 = kc*16;
            unsigned a[4];
            a[0] = *reinterpret_cast<const unsigned*>(As + (rb + grp    )*OSTR + k0 + 2*qd);
            a[1] = *reinterpret_cast<const unsigned*>(As + (rb + 8 + grp)*OSTR + k0 + 2*qd);
            a[2] = *reinterpret_cast<const unsigned*>(As + (rb + grp    )*OSTR + k0 + 2*qd + 8);
            a[3] = *reinterpret_cast<const unsigned*>(As + (rb + 8 + grp)*OSTR + k0 + 2*qd + 8);
            unsigned b[8][2];
            #pragma unroll
            for (int ni = 0; ni < 8; ni++) {
                int nb = wn*64 + ni*8 + grp;
                b[ni][0] = *reinterpret_cast<const unsigned*>(Bs + nb*OSTR + k0 + 2*qd);
                b[ni][1] = *reinterpret_cast<const unsigned*>(Bs + nb*OSTR + k0 + 2*qd + 8);
            }
            #pragma unroll
            for (int ni = 0; ni < 8; ni++)
                mma_bf16(d[ni], a, b[ni]);
        }

        #pragma unroll
        for (int ni = 0; ni < 8; ni++) {
            int n0 = wn*64 + ni*8 + qd*2;
            float* p0 = out + (size_t)(pixBase + row0)*CIN + n0;
            *reinterpret_cast<float2*>(p0) =
                make_float2(d[ni][0] + bo[ni][0], d[ni][1] + bo[ni][1]);
            *reinterpret_cast<float2*>(p0 + 8*CIN) =
                make_float2(d[ni][2] + bo[ni][0], d[ni][3] + bo[ni][1]);
        }
        __syncthreads();
    }
}

// ---------------------------------------------------------------------------
extern "C" void kernel_launch(void* const* d_in, const int* in_sizes, int n_in,
                              void* d_out, int out_size)
{
    const float* x2d   = (const float*)d_in[0];
    const float* lng   = (const float*)d_in[1];
    const float* lnb   = (const float*)d_in[2];
    const float* Wqkv  = (const float*)d_in[3];
    const float* Wbias = (const float*)d_in[4];
    const float* Wgate = (const float*)d_in[5];
    const float* bgate = (const float*)d_in[6];
    const float* Wout  = (const float*)d_in[7];
    const float* bout  = (const float*)d_in[8];
    float* out = (float*)d_out;

    const int smem1 = (64*OSTR + 128*OSTR) * 2;   // ~51 KB
    const int smem2 = (256*KSS + 32*VTS) * 2;     // ~37 KB
    const int smem3 = (64*OSTR + 128*OSTR) * 2;   // ~51 KB
    cudaFuncSetAttribute(k1_mma, cudaFuncAttributeMaxDynamicSharedMemorySize, smem1);
    cudaFuncSetAttribute(k2_mma, cudaFuncAttributeMaxDynamicSharedMemorySize, smem2);
    cudaFuncSetAttribute(k3_mma, cudaFuncAttributeMaxDynamicSharedMemorySize, smem3);

    k_prep<<<320, 256>>>(Wqkv, Wgate, Wout);
    k1_mma<<<1024, 256, smem1>>>(x2d, lng, lnb, Wbias, bgate);
    k2_mma<<<dim3(NN, NH), 256, smem2>>>();
    k3_mma<<<512, 256, smem3>>>(bout, out);
}

// round 16
// speedup vs baseline: 1.0604x; 1.0604x over previous
#include <cuda_runtime.h>
#include <cuda_bf16.h>

#define NN 256
#define CIN 128
#define CATT 32
#define NH 4
#define LN_EPS 1e-5f
#define KSS 40        // Ks bf16 stride (k2)
#define VTS 264       // Vt bf16 stride (k2)
#define OSTR 136      // bf16 smem stride (k1/k3)
#define LOG2E 1.4426950408889634f
#define QSC 0.25502551286804425f   // (1/sqrt(32))*log2e

// ---------------- scratch (device globals; allocation-free rule) ------------
__device__ __nv_bfloat16 g_q   [(size_t)NN*NH*NN*CATT];  // [i][h][j][c]
__device__ __nv_bfloat16 g_k   [(size_t)NN*NH*NN*CATT];
__device__ __nv_bfloat16 g_v   [(size_t)NN*NH*NN*CATT];
__device__ __nv_bfloat16 g_gate[(size_t)NN*NH*NN*CATT];
__device__ __nv_bfloat16 g_ao  [(size_t)NN*NH*NN*CATT];  // [i][h][j][c]
__device__ __nv_bfloat16 g_B2t [(size_t)NH*NN*NN];       // [h][j][k] * log2e, bf16
__device__ __nv_bfloat16 g_Wb  [4*128*128];              // bf16 [t][n][k] (k1)
__device__ __nv_bfloat16 g_Wo  [128*128];                // bf16 [n][k] (k3)

__device__ __forceinline__ float ex2(float x) {
    float y;
    asm("ex2.approx.ftz.f32 %0, %1;" : "=f"(y) : "f"(x));
    return y;
}
__device__ __forceinline__ unsigned pack_bf16(float lo, float hi) {
    unsigned r;
    asm("cvt.rn.bf16x2.f32 %0, %1, %2;" : "=r"(r) : "f"(hi), "f"(lo));
    return r;
}
__device__ __forceinline__ void mma_bf16(float* d, const unsigned* a, const unsigned* b) {
    asm volatile(
        "mma.sync.aligned.m16n8k16.row.col.f32.bf16.bf16.f32 "
        "{%0,%1,%2,%3}, {%4,%5,%6,%7}, {%8,%9}, {%0,%1,%2,%3};"
        : "+f"(d[0]), "+f"(d[1]), "+f"(d[2]), "+f"(d[3])
        : "r"(a[0]), "r"(a[1]), "r"(a[2]), "r"(a[3]), "r"(b[0]), "r"(b[1]));
}

// ---------------------------------------------------------------------------
// Weight prep: bf16 [t][n][k] (qkv/gate) and [n][k] (Wout, rows remapped)
// ---------------------------------------------------------------------------
__global__ void k_prep(const float* __restrict__ Wqkv,
                       const float* __restrict__ Wgate,
                       const float* __restrict__ Wout)
{
    int gid = blockIdx.x * 256 + threadIdx.x;
    if (gid >= 5 * 16384) return;
    int t = gid >> 14, r = gid & 16383, n = r >> 7, k = r & 127;
    if (t < 3) {
        float v = Wqkv[k*384 + (n & 31)*12 + t*4 + (n >> 5)];
        g_Wb[t*16384 + n*128 + k] = __float2bfloat16(v);
    } else if (t == 3) {
        float v = Wgate[k*128 + (n & 31)*4 + (n >> 5)];
        g_Wb[3*16384 + n*128 + k] = __float2bfloat16(v);
    } else {
        float v = Wout[((k & 31)*4 + (k >> 5))*128 + n];
        g_Wo[n*128 + k] = __float2bfloat16(v);
    }
}

// ---------------------------------------------------------------------------
// Kernel 1: LN (fused) + bf16 GEMM m16n8k16, 64 pixels x 4x128 cols, K=128.
// (R8 exact)
// ---------------------------------------------------------------------------
__global__ void __launch_bounds__(256, 3)
k1_mma(const float* __restrict__ x2d, const float* __restrict__ lng,
       const float* __restrict__ lnb, const float* __restrict__ Wbias,
       const float* __restrict__ bgate)
{
    extern __shared__ char smc[];
    __nv_bfloat16* As = reinterpret_cast<__nv_bfloat16*>(smc);             // [64][OSTR]
    __nv_bfloat16* Bs = reinterpret_cast<__nv_bfloat16*>(smc + 64*OSTR*2); // [128][OSTR]

    const int tid = threadIdx.x, lane = tid & 31, warp = tid >> 5;
    const int pixBase = blockIdx.x * 64;
    const int i = pixBase >> 8, j0 = pixBase & 255;

    // ---- LayerNorm warp-per-pixel + bias projection ----
    for (int p = warp; p < 64; p += 8) {
        const int pix = pixBase + p;
        float4 v = reinterpret_cast<const float4*>(x2d + (size_t)pix*CIN)[lane];
        float s  = v.x + v.y + v.z + v.w;
        float ss = v.x*v.x + v.y*v.y + v.z*v.z + v.w*v.w;
        #pragma unroll
        for (int o = 16; o > 0; o >>= 1) {
            s  += __shfl_xor_sync(0xffffffffu, s,  o);
            ss += __shfl_xor_sync(0xffffffffu, ss, o);
        }
        float mu   = s * (1.f/CIN);
        float rstd = rsqrtf(ss * (1.f/CIN) - mu*mu + LN_EPS);
        float4 g4 = reinterpret_cast<const float4*>(lng)[lane];
        float4 b4 = reinterpret_cast<const float4*>(lnb)[lane];
        float xn[4];
        xn[0] = (v.x - mu)*rstd*g4.x + b4.x;
        xn[1] = (v.y - mu)*rstd*g4.y + b4.y;
        xn[2] = (v.z - mu)*rstd*g4.z + b4.z;
        xn[3] = (v.w - mu)*rstd*g4.w + b4.w;

        unsigned* ap = reinterpret_cast<unsigned*>(As + p*OSTR + lane*4);
        ap[0] = pack_bf16(xn[0], xn[1]);
        ap[1] = pack_bf16(xn[2], xn[3]);

        float bs[NH] = {0.f, 0.f, 0.f, 0.f};
        #pragma unroll
        for (int c = 0; c < 4; c++) {
            float4 wb = reinterpret_cast<const float4*>(Wbias)[lane*4 + c];
            bs[0] += xn[c]*wb.x; bs[1] += xn[c]*wb.y;
            bs[2] += xn[c]*wb.z; bs[3] += xn[c]*wb.w;
        }
        #pragma unroll
        for (int o = 16; o > 0; o >>= 1) {
            #pragma unroll
            for (int h = 0; h < NH; h++) bs[h] += __shfl_xor_sync(0xffffffffu, bs[h], o);
        }
        if (lane < 4)
            g_B2t[((size_t)lane*NN + (pix & 255))*NN + (pix >> 8)] =
                __float2bfloat16(bs[lane] * LOG2E);
    }

    const int wm = warp >> 1, wn = warp & 1;
    const int grp = lane >> 2, qd = lane & 3;
    const int rb = wm*16;
    const int row0 = rb + grp;

    for (int tile = 0; tile < 4; tile++) {
        const __nv_bfloat16* Wt = g_Wb + tile*16384;
        for (int e = tid; e < 2048; e += 256) {
            int n = e >> 4, ch = e & 15;
            uint4 v = *reinterpret_cast<const uint4*>(Wt + n*128 + ch*8);
            *reinterpret_cast<uint4*>(Bs + n*OSTR + ch*8) = v;
        }
        __syncthreads();

        float d[8][4];
        #pragma unroll
        for (int ni = 0; ni < 8; ni++)
            #pragma unroll
            for (int r = 0; r < 4; r++) d[ni][r] = 0.f;

        #pragma unroll 2
        for (int kc = 0; kc < 8; kc++) {
            const int k0 = kc*16;
            unsigned a[4];
            a[0] = *reinterpret_cast<const unsigned*>(As + (rb + grp    )*OSTR + k0 + 2*qd);
            a[1] = *reinterpret_cast<const unsigned*>(As + (rb + 8 + grp)*OSTR + k0 + 2*qd);
            a[2] = *reinterpret_cast<const unsigned*>(As + (rb + grp    )*OSTR + k0 + 2*qd + 8);
            a[3] = *reinterpret_cast<const unsigned*>(As + (rb + 8 + grp)*OSTR + k0 + 2*qd + 8);
            unsigned b[8][2];
            #pragma unroll
            for (int ni = 0; ni < 8; ni++) {
                int nb = wn*64 + ni*8 + grp;
                b[ni][0] = *reinterpret_cast<const unsigned*>(Bs + nb*OSTR + k0 + 2*qd);
                b[ni][1] = *reinterpret_cast<const unsigned*>(Bs + nb*OSTR + k0 + 2*qd + 8);
            }
            #pragma unroll
            for (int ni = 0; ni < 8; ni++)
                mma_bf16(d[ni], a, b[ni]);
        }

        if (tile < 3) {
            __nv_bfloat16* dst = (tile == 0) ? g_q : (tile == 1) ? g_k : g_v;
            #pragma unroll
            for (int ni = 0; ni < 8; ni++) {
                int n0 = wn*64 + ni*8 + qd*2;
                int h = n0 >> 5, c = n0 & 31;
                __nv_bfloat16* p0 = dst + ((size_t)(i*NH + h)*NN + j0 + row0)*CATT + c;
                *reinterpret_cast<unsigned*>(p0)          = pack_bf16(d[ni][0], d[ni][1]);
                *reinterpret_cast<unsigned*>(p0 + 8*CATT) = pack_bf16(d[ni][2], d[ni][3]);
            }
        } else {
            #pragma unroll
            for (int ni = 0; ni < 8; ni++) {
                int n0 = wn*64 + ni*8 + qd*2;
                int h = n0 >> 5, c = n0 & 31;
                float bg0 = bgate[c*NH + h], bg1 = bgate[(c+1)*NH + h];
                __nv_bfloat16* p0 = g_gate + ((size_t)(i*NH + h)*NN + j0 + row0)*CATT + c;
                *reinterpret_cast<unsigned*>(p0) = pack_bf16(
                    1.f / (1.f + __expf(-(d[ni][0] + bg0))),
                    1.f / (1.f + __expf(-(d[ni][1] + bg1))));
                *reinterpret_cast<unsigned*>(p0 + 8*CATT) = pack_bf16(
                    1.f / (1.f + __expf(-(d[ni][2] + bg0))),
                    1.f / (1.f + __expf(-(d[ni][3] + bg1))));
            }
        }
        __syncthreads();
    }
}

// ---------------------------------------------------------------------------
// Kernel 2: bf16 flash attention. 32-key chunks (8 iterations): 2x the
// independent ops per phase vs 16-key chunks, for latency hiding.
// Accumulation order identical to the 16-key version (bit-exact).
// ---------------------------------------------------------------------------
__global__ void __launch_bounds__(256, 2)
k2_mma()
{
    extern __shared__ char smc[];
    __nv_bfloat16* Ks = reinterpret_cast<__nv_bfloat16*>(smc);            // [256][KSS]
    __nv_bfloat16* Vt = reinterpret_cast<__nv_bfloat16*>(smc + 256*KSS*2);// [32][VTS]

    const int i = blockIdx.x, h = blockIdx.y;
    const int tid = threadIdx.x;
    const size_t base = ((size_t)(i*NH + h))*NN*CATT;

    for (int e = tid; e < 1024; e += 256) {
        int row = e >> 2, c0 = (e & 3) * 8;
        uint4 v = *reinterpret_cast<const uint4*>(g_k + base + row*CATT + c0);
        *reinterpret_cast<uint4*>(Ks + row*KSS + c0) = v;
    }
    for (int e = tid; e < 1024; e += 256) {
        int lane32 = e & 31, grp32 = e >> 5;
        int c0 = (grp32 & 3) * 8, row = (grp32 >> 2) * 32 + lane32;
        uint4 v = *reinterpret_cast<const uint4*>(g_v + base + row*CATT + c0);
        __nv_bfloat16 tmp[8];
        *reinterpret_cast<uint4*>(tmp) = v;
        #pragma unroll
        for (int u = 0; u < 8; u++) Vt[(c0+u)*VTS + row] = tmp[u];
    }

    const int lane = tid & 31, warp = tid >> 5, grp = lane >> 2, qd = lane & 3;
    const int qb = warp*32;

    unsigned aq[2][2][4];
    {
        const __nv_bfloat16* qg = g_q + base;
        #pragma unroll
        for (int kc = 0; kc < 2; kc++)
            #pragma unroll
            for (int mi = 0; mi < 2; mi++) {
                int r0 = qb + mi*16 + grp;
                aq[kc][mi][0] = *reinterpret_cast<const unsigned*>(qg + r0*CATT     + kc*16 + 2*qd);
                aq[kc][mi][1] = *reinterpret_cast<const unsigned*>(qg + (r0+8)*CATT + kc*16 + 2*qd);
                aq[kc][mi][2] = *reinterpret_cast<const unsigned*>(qg + r0*CATT     + kc*16 + 2*qd + 8);
                aq[kc][mi][3] = *reinterpret_cast<const unsigned*>(qg + (r0+8)*CATT + kc*16 + 2*qd + 8);
            }
    }
    __syncthreads();

    float l[4] = {0.f, 0.f, 0.f, 0.f};
    float o[2][4][4];
    #pragma unroll
    for (int mi = 0; mi < 2; mi++)
        #pragma unroll
        for (int nj = 0; nj < 4; nj++)
            #pragma unroll
            for (int r = 0; r < 4; r++) o[mi][nj][r] = 0.f;

    const __nv_bfloat16* Bt = g_B2t + (size_t)h*NN*NN;

    for (int kb = 0; kb < NN; kb += 32) {
        // ---- S = Q K^T for 32 keys: 8 K-frag loads, 16 MMAs ----
        float s[2][4][4];
        #pragma unroll
        for (int mi = 0; mi < 2; mi++)
            #pragma unroll
            for (int ni = 0; ni < 4; ni++)
                #pragma unroll
                for (int r = 0; r < 4; r++) s[mi][ni][r] = 0.f;

        #pragma unroll
        for (int kc = 0; kc < 2; kc++)
            #pragma unroll
            for (int ni = 0; ni < 4; ni++) {
                const __nv_bfloat16* kp = Ks + (kb + ni*8 + grp)*KSS + kc*16 + 2*qd;
                unsigned b[2];
                b[0] = *reinterpret_cast<const unsigned*>(kp);
                b[1] = *reinterpret_cast<const unsigned*>(kp + 8);
                mma_bf16(s[0][ni], aq[kc][0], b);
                mma_bf16(s[1][ni], aq[kc][1], b);
            }

        // ---- p = 2^(s*qsc + bias_l2e): 8 indep bias loads, 32 ex2 ----
        unsigned aP[2][2][4];   // [mi][kc2]: A-frags for PV (keys kc2*16..+15)
        #pragma unroll
        for (int mi = 0; mi < 2; mi++) {
            int r0 = qb + mi*16 + grp;
            float pv[4][4];
            #pragma unroll
            for (int ni = 0; ni < 4; ni++) {
                __nv_bfloat162 bA = *reinterpret_cast<const __nv_bfloat162*>(
                    Bt + (size_t)r0*NN + kb + ni*8 + 2*qd);
                __nv_bfloat162 bB = *reinterpret_cast<const __nv_bfloat162*>(
                    Bt + (size_t)(r0+8)*NN + kb + ni*8 + 2*qd);
                pv[ni][0] = ex2(fmaf(s[mi][ni][0], QSC, __bfloat162float(bA.x)));
                pv[ni][1] = ex2(fmaf(s[mi][ni][1], QSC, __bfloat162float(bA.y)));
                pv[ni][2] = ex2(fmaf(s[mi][ni][2], QSC, __bfloat162float(bB.x)));
                pv[ni][3] = ex2(fmaf(s[mi][ni][3], QSC, __bfloat162float(bB.y)));
                l[2*mi]   += pv[ni][0] + pv[ni][1];
                l[2*mi+1] += pv[ni][2] + pv[ni][3];
            }
            #pragma unroll
            for (int kc2 = 0; kc2 < 2; kc2++) {
                aP[mi][kc2][0] = pack_bf16(pv[2*kc2  ][0], pv[2*kc2  ][1]);
                aP[mi][kc2][1] = pack_bf16(pv[2*kc2  ][2], pv[2*kc2  ][3]);
                aP[mi][kc2][2] = pack_bf16(pv[2*kc2+1][0], pv[2*kc2+1][1]);
                aP[mi][kc2][3] = pack_bf16(pv[2*kc2+1][2], pv[2*kc2+1][3]);
            }
        }

        // ---- O += P V: 8 V-frag loads, 16 MMAs ----
        #pragma unroll
        for (int kc2 = 0; kc2 < 2; kc2++)
            #pragma unroll
            for (int nj = 0; nj < 4; nj++) {
                const __nv_bfloat16* vp = Vt + (nj*8 + grp)*VTS + kb + kc2*16 + 2*qd;
                unsigned b[2];
                b[0] = *reinterpret_cast<const unsigned*>(vp);
                b[1] = *reinterpret_cast<const unsigned*>(vp + 8);
                mma_bf16(o[0][nj], aP[0][kc2], b);
                mma_bf16(o[1][nj], aP[1][kc2], b);
            }
    }

    float rl[4];
    #pragma unroll
    for (int r = 0; r < 4; r++) {
        l[r] += __shfl_xor_sync(0xffffffffu, l[r], 1);
        l[r] += __shfl_xor_sync(0xffffffffu, l[r], 2);
        rl[r] = 1.f / l[r];
    }
    #pragma unroll
    for (int mi = 0; mi < 2; mi++) {
        int r0 = qb + mi*16 + grp;
        #pragma unroll
        for (int nj = 0; nj < 4; nj++) {
            int c0 = nj*8 + 2*qd;
            __nv_bfloat162 g0 = *reinterpret_cast<const __nv_bfloat162*>(g_gate + base + (size_t)r0*CATT + c0);
            __nv_bfloat162 g1 = *reinterpret_cast<const __nv_bfloat162*>(g_gate + base + (size_t)(r0+8)*CATT + c0);
            *reinterpret_cast<unsigned*>(g_ao + base + (size_t)r0*CATT + c0) =
                pack_bf16(o[mi][nj][0]*rl[2*mi]  *__bfloat162float(g0.x),
                          o[mi][nj][1]*rl[2*mi]  *__bfloat162float(g0.y));
            *reinterpret_cast<unsigned*>(g_ao + base + (size_t)(r0+8)*CATT + c0) =
                pack_bf16(o[mi][nj][2]*rl[2*mi+1]*__bfloat162float(g1.x),
                          o[mi][nj][3]*rl[2*mi+1]*__bfloat162float(g1.y));
        }
    }
}

// ---------------------------------------------------------------------------
// Kernel 3: out = ao @ Wo + b_out (bf16 mma, R8 exact). 2 M-tiles per CTA.
// ---------------------------------------------------------------------------
__global__ void __launch_bounds__(256, 2)
k3_mma(const float* __restrict__ bout, float* __restrict__ out)
{
    extern __shared__ char smc[];
    __nv_bfloat16* As = reinterpret_cast<__nv_bfloat16*>(smc);            // [64][OSTR]
    __nv_bfloat16* Bs = reinterpret_cast<__nv_bfloat16*>(smc + 64*OSTR*2);// [128][OSTR] ([n][k])

    const int tid = threadIdx.x;
    const int warp = tid >> 5, lane = tid & 31;
    const int wm = warp >> 1, wn = warp & 1;
    const int grp = lane >> 2, qd = lane & 3;
    const int row0 = wm*16 + grp;
    const int rb = wm*16;

    for (int e = tid; e < 2048; e += 256) {
        int n = e >> 4, ch = e & 15;
        uint4 v = *reinterpret_cast<const uint4*>(g_Wo + n*128 + ch*8);
        *reinterpret_cast<uint4*>(Bs + n*OSTR + ch*8) = v;
    }

    float bo[8][2];
    #pragma unroll
    for (int ni = 0; ni < 8; ni++) {
        int n0 = wn*64 + ni*8 + qd*2;
        bo[ni][0] = bout[n0]; bo[ni][1] = bout[n0+1];
    }

    for (int mt = 0; mt < 2; mt++) {
        const int pixBase = blockIdx.x * 128 + mt * 64;
        const int i = pixBase >> 8, j0 = pixBase & 255;

        for (int e = tid; e < 1024; e += 256) {
            int m = e >> 4, u = e & 15, h = u >> 2, c8 = (u & 3) * 8;
            uint4 v = *reinterpret_cast<const uint4*>(
                g_ao + ((size_t)(i*NH + h)*NN + j0 + m)*CATT + c8);
            *reinterpret_cast<uint4*>(As + m*OSTR + h*32 + c8) = v;
        }
        __syncthreads();

        float d[8][4];
        #pragma unroll
        for (int ni = 0; ni < 8; ni++)
            #pragma unroll
            for (int r = 0; r < 4; r++) d[ni][r] = 0.f;

        #pragma unroll 2
        for (int kc = 0; kc < 8; kc++) {
            const int k0 = kc*16;
            unsigned a[4];
            a[0] = *reinterpret_cast<const unsigned*>(As + (rb + grp    )*OSTR + k0 + 2*qd);
            a[1] = *reinterpret_cast<const unsigned*>(As + (rb + 8 + grp)*OSTR + k0 + 2*qd);
            a[2] = *reinterpret_cast<const unsigned*>(As + (rb + grp    )*OSTR + k0 + 2*qd + 8);
            a[3] = *reinterpret_cast<const unsigned*>(As + (rb + 8 + grp)*OSTR + k0 + 2*qd + 8);
            unsigned b[8][2];
            #pragma unroll
            for (int ni = 0; ni < 8; ni++) {
                int nb = wn*64 + ni*8 + grp;
                b[ni][0] = *reinterpret_cast<const unsigned*>(Bs + nb*OSTR + k0 + 2*qd);
                b[ni][1] = *reinterpret_cast<const unsigned*>(Bs + nb*OSTR + k0 + 2*qd + 8);
            }
            #pragma unroll
            for (int ni = 0; ni < 8; ni++)
                mma_bf16(d[ni], a, b[ni]);
        }

        #pragma unroll
        for (int ni = 0; ni < 8; ni++) {
            int n0 = wn*64 + ni*8 + qd*2;
            float* p0 = out + (size_t)(pixBase + row0)*CIN + n0;
            *reinterpret_cast<float2*>(p0) =
                make_float2(d[ni][0] + bo[ni][0], d[ni][1] + bo[ni][1]);
            *reinterpret_cast<float2*>(p0 + 8*CIN) =
                make_float2(d[ni][2] + bo[ni][0], d[ni][3] + bo[ni][1]);
        }
        __syncthreads();
    }
}

// ---------------------------------------------------------------------------
extern "C" void kernel_launch(void* const* d_in, const int* in_sizes, int n_in,
                              void* d_out, int out_size)
{
    const float* x2d   = (const float*)d_in[0];
    const float* lng   = (const float*)d_in[1];
    const float* lnb   = (const float*)d_in[2];
    const float* Wqkv  = (const float*)d_in[3];
    const float* Wbias = (const float*)d_in[4];
    const float* Wgate = (const float*)d_in[5];
    const float* bgate = (const float*)d_in[6];
    const float* Wout  = (const float*)d_in[7];
    const float* bout  = (const float*)d_in[8];
    float* out = (float*)d_out;

    const int smem1 = (64*OSTR + 128*OSTR) * 2;   // ~51 KB
    const int smem2 = (256*KSS + 32*VTS) * 2;     // ~37 KB
    const int smem3 = (64*OSTR + 128*OSTR) * 2;   // ~51 KB
    cudaFuncSetAttribute(k1_mma, cudaFuncAttributeMaxDynamicSharedMemorySize, smem1);
    cudaFuncSetAttribute(k2_mma, cudaFuncAttributeMaxDynamicSharedMemorySize, smem2);
    cudaFuncSetAttribute(k3_mma, cudaFuncAttributeMaxDynamicSharedMemorySize, smem3);

    k_prep<<<320, 256>>>(Wqkv, Wgate, Wout);
    k1_mma<<<1024, 256, smem1>>>(x2d, lng, lnb, Wbias, bgate);
    k2_mma<<<dim3(NN, NH), 256, smem2>>>();
    k3_mma<<<512, 256, smem3>>>(bout, out);
}